// round 4
// baseline (speedup 1.0000x reference)
#include <cuda_runtime.h>
#include <cuda_fp16.h>

// Problem constants
#define BATCH 128
#define NIN   1152
#define DIN   8
#define NOUT  10
#define DDIM  16
#define FDIM  160
#define ROWSZ ((size_t)NIN * FDIM)
#define SQ_EPS 1e-7f

#define GRP     4            // i's per k1 block
#define NIG     (NIN / GRP)  // 288 i-groups
#define BQ      32           // b's per k1 block
#define K1_BLOCKS (NIG * (BATCH / BQ))   // 1152

#define K2_THREADS 768
#define K2_WARPS   24
#define I_PER_WARP 48
#define K2_ITERS   16

typedef unsigned long long ull;

// u_hat: [BATCH][NIN][FDIM] fp16 = 47.2 MB
__device__ __half g_uhat[(size_t)BATCH * ROWSZ];
// pass-0 partial sums: [slab][b][f] fp32 = 23.6 MB
__device__ float g_part[NIG][BATCH][FDIM];

// ---------------- packed f32x2 helpers -------------------------------------
__device__ __forceinline__ ull pk2(float lo, float hi) {
    ull r; asm("mov.b64 %0, {%1, %2};" : "=l"(r) : "f"(lo), "f"(hi)); return r;
}
__device__ __forceinline__ void upk2(ull v, float& lo, float& hi) {
    asm("mov.b64 {%0, %1}, %2;" : "=f"(lo), "=f"(hi) : "l"(v));
}
__device__ __forceinline__ ull fma2(ull a, ull b, ull c) {
    ull d; asm("fma.rn.f32x2 %0, %1, %2, %3;" : "=l"(d) : "l"(a), "l"(b), "l"(c)); return d;
}
__device__ __forceinline__ ull mul2(ull a, ull b) {
    ull d; asm("mul.rn.f32x2 %0, %1, %2;" : "=l"(d) : "l"(a), "l"(b)); return d;
}
__device__ __forceinline__ ull add2(ull a, ull b) {
    ull d; asm("add.rn.f32x2 %0, %1, %2;" : "=l"(d) : "l"(a), "l"(b)); return d;
}
__device__ __forceinline__ ull h2_to_f2(unsigned h2) {
    ull r;
    asm("{\n\t"
        ".reg .b16 l, h;\n\t"
        ".reg .f32 fl, fh;\n\t"
        "mov.b32 {l, h}, %1;\n\t"
        "cvt.f32.f16 fl, l;\n\t"
        "cvt.f32.f16 fh, h;\n\t"
        "mov.b64 %0, {fl, fh};\n\t"
        "}" : "=l"(r) : "r"(h2));
    return r;
}

// ---------------------------------------------------------------------------
// K1: block = (i-group of 4, b-quarter of 32). Thread = (f-pair, 4 b-pairs).
// f32x2 math b-paired; coalesced half2 stores; accumulates pass-0 partial
// sums over its 4 i's in registers and writes them to g_part.
// ---------------------------------------------------------------------------
__global__ __launch_bounds__(320) void k1_uhat(const float* __restrict__ x,
                                               const float* __restrict__ W) {
    const int bx = blockIdx.x;
    const int ig = bx >> 2;          // 0..287
    const int bq = bx & 3;           // 0..3
    const int i0 = ig * GRP;
    const int bstart = bq * BQ;

    __shared__ __align__(16) float Ws[GRP][FDIM * DIN];   // 20 KB
    __shared__ __align__(16) float xt[GRP][DIN][BQ];      // 4 KB

    const int tid = threadIdx.x;

    for (int t = tid; t < GRP * FDIM * DIN; t += 320)
        Ws[t / (FDIM * DIN)][t % (FDIM * DIN)] = W[(size_t)i0 * (FDIM * DIN) + t];
    for (int t = tid; t < GRP * DIN * BQ; t += 320) {
        const int b = t & (BQ - 1);
        const int k = (t >> 5) & 7;
        const int ii = t >> 8;
        xt[ii][k][b] = x[((size_t)(bstart + b) * NIN + i0 + ii) * DIN + k];
    }
    __syncthreads();

    const int f2    = tid % 80;      // f-pair: fA=2*f2, fB=2*f2+1
    const int phase = tid / 80;      // 0..3, owns 4 b-pairs
    const int fA = 2 * f2;
    const int fB = 2 * f2 + 1;

    // s partial accumulators: per b-pair, (b0,b1) packed, for fA and fB
    ull sA2[4], sB2[4];
#pragma unroll
    for (int p = 0; p < 4; p++) { sA2[p] = 0ull; sB2[p] = 0ull; }

    for (int ii = 0; ii < GRP; ++ii) {
        // load + pack weights for this i (broadcast-duplicated for b-pair fma2)
        ull wA2[DIN], wB2[DIN];
#pragma unroll
        for (int k = 0; k < DIN; k++) {
            const float wa = Ws[ii][fA * DIN + k];
            const float wb = Ws[ii][fB * DIN + k];
            wA2[k] = pk2(wa, wa);
            wB2[k] = pk2(wb, wb);
        }
        const int i = i0 + ii;
        __half2* __restrict__ ust = reinterpret_cast<__half2*>(
            g_uhat + (size_t)i * FDIM) + f2;

#pragma unroll
        for (int p = 0; p < 4; ++p) {
            const int lb0 = (phase * 4 + p) * 2;      // local b (even)
            const int b0  = bstart + lb0;
            // x pair (b0,b1) per k
            ull uA = mul2(wA2[0], *reinterpret_cast<const ull*>(&xt[ii][0][lb0]));
            ull uB = mul2(wB2[0], *reinterpret_cast<const ull*>(&xt[ii][0][lb0]));
#pragma unroll
            for (int k = 1; k < DIN; k++) {
                const ull x2 = *reinterpret_cast<const ull*>(&xt[ii][k][lb0]);
                uA = fma2(wA2[k], x2, uA);
                uB = fma2(wB2[k], x2, uB);
            }
            sA2[p] = add2(sA2[p], uA);
            sB2[p] = add2(sB2[p], uB);
            float a0, a1, c0, c1;
            upk2(uA, a0, a1);
            upk2(uB, c0, c1);
            ust[(size_t)b0 * (ROWSZ / 2)]       = __floats2half2_rn(a0, c0);
            ust[(size_t)(b0 + 1) * (ROWSZ / 2)] = __floats2half2_rn(a1, c1);
        }
    }

    // write pass-0 partials: g_part[ig][b][fA..fB]
#pragma unroll
    for (int p = 0; p < 4; ++p) {
        const int b0 = bstart + (phase * 4 + p) * 2;
        float a0, a1, c0, c1;
        upk2(sA2[p], a0, a1);
        upk2(sB2[p], c0, c1);
        *reinterpret_cast<ull*>(&g_part[ig][b0][fA])     = pk2(a0, c0);
        *reinterpret_cast<ull*>(&g_part[ig][b0 + 1][fA]) = pk2(a1, c1);
    }
}

// ---------------------------------------------------------------------------
// K2: init (reduce 288 slabs -> s0 -> v0), then 2 routing passes over u_hat.
// ---------------------------------------------------------------------------
__global__ __launch_bounds__(K2_THREADS) void k2_route(const float* __restrict__ bias,
                                                       float* __restrict__ out) {
    const int b   = blockIdx.x;
    const int tid = threadIdx.x;
    const int w   = tid >> 5;
    const int l   = tid & 31;
    const bool active = (l < 30);
    const int g = active ? (l / 10) : 0;
    const int j = active ? (l % 10) : 0;

    __shared__ float s_part[K2_WARPS][FDIM];  // 15 KB
    __shared__ float s_red[FDIM];
    __shared__ float vsum_sm[FDIM];
    __shared__ float vlast_sm[FDIM];
    __shared__ float bias_sm[FDIM];

    if (tid < FDIM) bias_sm[tid] = bias[tid];

    // ---- init: reduce pass-0 partials (288 slabs) ----
    if (tid < 640) {
        const int q = tid / FDIM;          // 0..3
        const int f = tid % FDIM;
        float acc = 0.f;
        const float* __restrict__ p = &g_part[q * (NIG / 4)][b][f];
        for (int s = 0; s < NIG / 4; ++s)
            acc += p[(size_t)s * (BATCH * FDIM)];
        s_part[q][f] = acc;
    }
    __syncthreads();
    if (tid < FDIM) {
        const float acc = s_part[0][tid] + s_part[1][tid] +
                          s_part[2][tid] + s_part[3][tid];
        s_red[tid] = acc * (1.0f / NOUT) + bias_sm[tid];
    }
    __syncthreads();
    if (tid < NOUT) {
        float sv[DDIM];
        float sq = 0.f;
#pragma unroll
        for (int d = 0; d < DDIM; d++) {
            sv[d] = s_red[tid * DDIM + d];
            sq = fmaf(sv[d], sv[d], sq);
        }
        const float scale = sq / (1.0f + sq) * rsqrtf(sq + SQ_EPS);
#pragma unroll
        for (int d = 0; d < DDIM; d++)
            vsum_sm[tid * DDIM + d] = scale * sv[d];   // v0
    }
    __syncthreads();

    const __half* __restrict__ ubase = g_uhat + (size_t)b * ROWSZ;
    const unsigned FULL = 0xFFFFFFFFu;

    for (int pass = 1; pass < 3; ++pass) {
        ull vr2[8];
#pragma unroll
        for (int m = 0; m < 8; m++)
            vr2[m] = pk2(vsum_sm[j * DDIM + 2 * m], vsum_sm[j * DDIM + 2 * m + 1]);
        ull sacc2[8];
#pragma unroll
        for (int m = 0; m < 8; m++) sacc2[m] = 0ull;

        uint4 p0 = make_uint4(0, 0, 0, 0), p1 = make_uint4(0, 0, 0, 0);
        {
            const int i = w * I_PER_WARP + g;
            if (active) {
                const uint4* up = reinterpret_cast<const uint4*>(
                    ubase + (size_t)i * FDIM + j * DDIM);
                p0 = up[0]; p1 = up[1];
            }
        }

        for (int it = 0; it < K2_ITERS; ++it) {
            uint4 n0 = make_uint4(0, 0, 0, 0), n1 = make_uint4(0, 0, 0, 0);
            if (it + 1 < K2_ITERS && active) {
                const int ni = w * I_PER_WARP + (it + 1) * 3 + g;
                const uint4* up = reinterpret_cast<const uint4*>(
                    ubase + (size_t)ni * FDIM + j * DDIM);
                n0 = up[0]; n1 = up[1];
            }

            ull u2[8];
            u2[0] = h2_to_f2(p0.x); u2[1] = h2_to_f2(p0.y);
            u2[2] = h2_to_f2(p0.z); u2[3] = h2_to_f2(p0.w);
            u2[4] = h2_to_f2(p1.x); u2[5] = h2_to_f2(p1.y);
            u2[6] = h2_to_f2(p1.z); u2[7] = h2_to_f2(p1.w);

            // logit a = u . vsum
            ull a2 = mul2(u2[0], vr2[0]);
#pragma unroll
            for (int m = 1; m < 8; m++) a2 = fma2(u2[m], vr2[m], a2);
            float alo, ahi; upk2(a2, alo, ahi);
            float a = alo + ahi;
            a = fmaxf(fminf(a, 60.f), -60.f);
            const float e = __expf(a);
            float esum = 0.f;
#pragma unroll
            for (int jj = 0; jj < NOUT; jj++)
                esum += __shfl_sync(FULL, e, g * 10 + jj);
            const float c = __fdividef(e, esum);
            const ull c2 = pk2(c, c);
#pragma unroll
            for (int m = 0; m < 8; m++) sacc2[m] = fma2(c2, u2[m], sacc2[m]);

            p0 = n0; p1 = n1;
        }

#pragma unroll
        for (int m = 0; m < 8; m++) {
            const ull t1 = __shfl_down_sync(FULL, sacc2[m], 10);
            const ull t2 = __shfl_down_sync(FULL, sacc2[m], 20);
            sacc2[m] = add2(sacc2[m], add2(t1, t2));
        }
        if (l < NOUT) {
#pragma unroll
            for (int m = 0; m < 8; m++)
                *reinterpret_cast<ull*>(&s_part[w][l * DDIM + 2 * m]) = sacc2[m];
        }
        __syncthreads();

        if (tid < FDIM) {
            float acc = 0.f;
#pragma unroll
            for (int ww = 0; ww < K2_WARPS; ww++) acc += s_part[ww][tid];
            s_red[tid] = acc + bias_sm[tid];
        }
        __syncthreads();

        if (tid < NOUT) {
            float sv[DDIM];
            float sq = 0.f;
#pragma unroll
            for (int d = 0; d < DDIM; d++) {
                sv[d] = s_red[tid * DDIM + d];
                sq = fmaf(sv[d], sv[d], sq);
            }
            const float scale = sq / (1.0f + sq) * rsqrtf(sq + SQ_EPS);
#pragma unroll
            for (int d = 0; d < DDIM; d++) {
                const float v = scale * sv[d];
                vlast_sm[tid * DDIM + d] = v;
                if (pass == 1) vsum_sm[tid * DDIM + d] += v;
            }
        }
        __syncthreads();
    }

    if (tid < FDIM) out[(size_t)b * FDIM + tid] = vlast_sm[tid];
}

// ---------------------------------------------------------------------------
extern "C" void kernel_launch(void* const* d_in, const int* in_sizes, int n_in,
                              void* d_out, int out_size) {
    const float* x = nullptr;
    const float* W = nullptr;
    const float* bias = nullptr;
    for (int idx = 0; idx < n_in; ++idx) {
        if (in_sizes[idx] == BATCH * NIN * DIN)             x    = (const float*)d_in[idx];
        else if (in_sizes[idx] == NIN * NOUT * DDIM * DIN)  W    = (const float*)d_in[idx];
        else if (in_sizes[idx] == NOUT * DDIM)              bias = (const float*)d_in[idx];
    }
    k1_uhat<<<K1_BLOCKS, 320>>>(x, W);
    k2_route<<<BATCH, K2_THREADS>>>(bias, (float*)d_out);
}

// round 5
// speedup vs baseline: 1.6156x; 1.6156x over previous
#include <cuda_runtime.h>
#include <cuda_fp16.h>

// Problem constants
#define BATCH 128
#define NIN   1152
#define DIN   8
#define NOUT  10
#define DDIM  16
#define FDIM  160
#define ROWSZ ((size_t)NIN * FDIM)
#define SQ_EPS 1e-7f

#define K2_THREADS 768
#define K2_WARPS   24
#define I_PER_WARP 48
#define K2_ITERS   16

typedef unsigned long long ull;

// u_hat scratch: [BATCH][NIN][FDIM] fp16 = 47.2 MB (L2-resident)
__device__ __half g_uhat[(size_t)BATCH * ROWSZ];

// ---------------- packed f32x2 helpers -------------------------------------
__device__ __forceinline__ ull pk2(float lo, float hi) {
    ull r; asm("mov.b64 %0, {%1, %2};" : "=l"(r) : "f"(lo), "f"(hi)); return r;
}
__device__ __forceinline__ void upk2(ull v, float& lo, float& hi) {
    asm("mov.b64 {%0, %1}, %2;" : "=f"(lo), "=f"(hi) : "l"(v));
}
__device__ __forceinline__ ull fma2(ull a, ull b, ull c) {
    ull d; asm("fma.rn.f32x2 %0, %1, %2, %3;" : "=l"(d) : "l"(a), "l"(b), "l"(c)); return d;
}
__device__ __forceinline__ ull mul2(ull a, ull b) {
    ull d; asm("mul.rn.f32x2 %0, %1, %2;" : "=l"(d) : "l"(a), "l"(b)); return d;
}
__device__ __forceinline__ ull add2(ull a, ull b) {
    ull d; asm("add.rn.f32x2 %0, %1, %2;" : "=l"(d) : "l"(a), "l"(b)); return d;
}
__device__ __forceinline__ ull h2_to_f2(unsigned h2) {
    ull r;
    asm("{\n\t"
        ".reg .b16 l, h;\n\t"
        ".reg .f32 fl, fh;\n\t"
        "mov.b32 {l, h}, %1;\n\t"
        "cvt.f32.f16 fl, l;\n\t"
        "cvt.f32.f16 fh, h;\n\t"
        "mov.b64 %0, {fl, fh};\n\t"
        "}" : "=l"(r) : "r"(h2));
    return r;
}

// ---------------------------------------------------------------------------
// K1: u_hat[b,i,f] = sum_k W[i,f,k] * x[b,i,k], fp16 store.
// One block per i (W read exactly once). Thread owns an (f-pair, b-pair)
// 2x2 micro-tile: 16 fma2 (=32 FMA) per tile, then cross-pack into two
// coalesced half2 stores (one per b).
// ---------------------------------------------------------------------------
__global__ __launch_bounds__(320) void k1_uhat(const float* __restrict__ x,
                                               const float* __restrict__ W) {
    const int i = blockIdx.x;                 // 0..1151
    __shared__ __align__(16) float Ws[FDIM * DIN];   // 5 KB
    __shared__ __align__(16) float xt[DIN][BATCH];   // 4 KB, transposed [k][b]
    const int tid = threadIdx.x;

    for (int t = tid; t < FDIM * DIN; t += 320)
        Ws[t] = W[(size_t)i * (FDIM * DIN) + t];
    for (int t = tid; t < BATCH * DIN; t += 320) {
        const int b = t >> 3, k = t & 7;
        xt[k][b] = x[((size_t)b * NIN + i) * DIN + k];
    }
    __syncthreads();

    const int f2    = tid % 80;   // f-pair: fA=2*f2, fB=2*f2+1
    const int phase = tid / 80;   // 0..3
    const int fA = 2 * f2;
    const int fB = 2 * f2 + 1;

    ull wA2[DIN], wB2[DIN];
#pragma unroll
    for (int k = 0; k < DIN; k++) {
        const float wa = Ws[fA * DIN + k];
        const float wb = Ws[fB * DIN + k];
        wA2[k] = pk2(wa, wa);
        wB2[k] = pk2(wb, wb);
    }

    // half2 view: element f2 within row (i, b)
    __half2* __restrict__ ust =
        reinterpret_cast<__half2*>(g_uhat + (size_t)i * FDIM) + f2;

    for (int p = phase; p < BATCH / 2; p += 4) {
        const int b0 = 2 * p;
        const ull x20 = *reinterpret_cast<const ull*>(&xt[0][b0]);
        ull uA = mul2(wA2[0], x20);
        ull uB = mul2(wB2[0], x20);
#pragma unroll
        for (int k = 1; k < DIN; k++) {
            const ull x2 = *reinterpret_cast<const ull*>(&xt[k][b0]);
            uA = fma2(wA2[k], x2, uA);
            uB = fma2(wB2[k], x2, uB);
        }
        float a0, a1, c0, c1;
        upk2(uA, a0, a1);     // (fA,b0), (fA,b1)
        upk2(uB, c0, c1);     // (fB,b0), (fB,b1)
        ust[(size_t)b0 * (ROWSZ / 2)]       = __floats2half2_rn(a0, c0);
        ust[(size_t)(b0 + 1) * (ROWSZ / 2)] = __floats2half2_rn(a1, c1);
    }
}

// ---------------------------------------------------------------------------
// K2: fused 3-iteration dynamic routing, one block (768 thr) per b.
// (identical to R3 — measured 32.7 us)
// ---------------------------------------------------------------------------
__global__ __launch_bounds__(K2_THREADS) void k2_route(const float* __restrict__ bias,
                                                       float* __restrict__ out) {
    const int b   = blockIdx.x;
    const int tid = threadIdx.x;
    const int w   = tid >> 5;
    const int l   = tid & 31;
    const bool active = (l < 30);
    const int g = active ? (l / 10) : 0;
    const int j = active ? (l % 10) : 0;

    __shared__ float s_part[K2_WARPS][FDIM];
    __shared__ float s_red[FDIM];
    __shared__ float vsum_sm[FDIM];
    __shared__ float vlast_sm[FDIM];
    __shared__ float bias_sm[FDIM];

    if (tid < FDIM) bias_sm[tid] = bias[tid];

    const __half* __restrict__ ubase = g_uhat + (size_t)b * ROWSZ;
    const unsigned FULL = 0xFFFFFFFFu;

    for (int pass = 0; pass < 3; ++pass) {
        ull vr2[8];
        if (pass > 0) {
#pragma unroll
            for (int m = 0; m < 8; m++)
                vr2[m] = pk2(vsum_sm[j * DDIM + 2 * m], vsum_sm[j * DDIM + 2 * m + 1]);
        }
        ull sacc2[8];
#pragma unroll
        for (int m = 0; m < 8; m++) sacc2[m] = 0ull;

        uint4 p0 = make_uint4(0, 0, 0, 0), p1 = make_uint4(0, 0, 0, 0);
        {
            const int i = w * I_PER_WARP + g;
            if (active) {
                const uint4* up = reinterpret_cast<const uint4*>(
                    ubase + (size_t)i * FDIM + j * DDIM);
                p0 = up[0]; p1 = up[1];
            }
        }

        for (int it = 0; it < K2_ITERS; ++it) {
            uint4 n0 = make_uint4(0, 0, 0, 0), n1 = make_uint4(0, 0, 0, 0);
            if (it + 1 < K2_ITERS && active) {
                const int ni = w * I_PER_WARP + (it + 1) * 3 + g;
                const uint4* up = reinterpret_cast<const uint4*>(
                    ubase + (size_t)ni * FDIM + j * DDIM);
                n0 = up[0]; n1 = up[1];
            }

            ull u2[8];
            u2[0] = h2_to_f2(p0.x); u2[1] = h2_to_f2(p0.y);
            u2[2] = h2_to_f2(p0.z); u2[3] = h2_to_f2(p0.w);
            u2[4] = h2_to_f2(p1.x); u2[5] = h2_to_f2(p1.y);
            u2[6] = h2_to_f2(p1.z); u2[7] = h2_to_f2(p1.w);

            if (pass == 0) {
#pragma unroll
                for (int m = 0; m < 8; m++) sacc2[m] = add2(sacc2[m], u2[m]);
            } else {
                ull a2 = mul2(u2[0], vr2[0]);
#pragma unroll
                for (int m = 1; m < 8; m++) a2 = fma2(u2[m], vr2[m], a2);
                float alo, ahi; upk2(a2, alo, ahi);
                float a = alo + ahi;
                a = fmaxf(fminf(a, 60.f), -60.f);
                const float e = __expf(a);
                float esum = 0.f;
#pragma unroll
                for (int jj = 0; jj < NOUT; jj++)
                    esum += __shfl_sync(FULL, e, g * 10 + jj);
                const float c = __fdividef(e, esum);
                const ull c2 = pk2(c, c);
#pragma unroll
                for (int m = 0; m < 8; m++) sacc2[m] = fma2(c2, u2[m], sacc2[m]);
            }
            p0 = n0; p1 = n1;
        }

#pragma unroll
        for (int m = 0; m < 8; m++) {
            const ull t1 = __shfl_down_sync(FULL, sacc2[m], 10);
            const ull t2 = __shfl_down_sync(FULL, sacc2[m], 20);
            sacc2[m] = add2(sacc2[m], add2(t1, t2));
        }
        if (l < NOUT) {
#pragma unroll
            for (int m = 0; m < 8; m++)
                *reinterpret_cast<ull*>(&s_part[w][l * DDIM + 2 * m]) = sacc2[m];
        }
        __syncthreads();

        if (tid < FDIM) {
            float acc = 0.f;
#pragma unroll
            for (int ww = 0; ww < K2_WARPS; ww++) acc += s_part[ww][tid];
            if (pass == 0) acc *= (1.0f / NOUT);
            s_red[tid] = acc + bias_sm[tid];
        }
        __syncthreads();

        if (tid < NOUT) {
            float sv[DDIM];
            float sq = 0.f;
#pragma unroll
            for (int d = 0; d < DDIM; d++) {
                sv[d] = s_red[tid * DDIM + d];
                sq = fmaf(sv[d], sv[d], sq);
            }
            const float scale = sq / (1.0f + sq) * rsqrtf(sq + SQ_EPS);
#pragma unroll
            for (int d = 0; d < DDIM; d++) {
                const float v = scale * sv[d];
                vlast_sm[tid * DDIM + d] = v;
                if (pass == 0)      vsum_sm[tid * DDIM + d] = v;
                else if (pass == 1) vsum_sm[tid * DDIM + d] += v;
            }
        }
        __syncthreads();
    }

    if (tid < FDIM) out[(size_t)b * FDIM + tid] = vlast_sm[tid];
}

// ---------------------------------------------------------------------------
extern "C" void kernel_launch(void* const* d_in, const int* in_sizes, int n_in,
                              void* d_out, int out_size) {
    const float* x = nullptr;
    const float* W = nullptr;
    const float* bias = nullptr;
    for (int idx = 0; idx < n_in; ++idx) {
        if (in_sizes[idx] == BATCH * NIN * DIN)             x    = (const float*)d_in[idx];
        else if (in_sizes[idx] == NIN * NOUT * DDIM * DIN)  W    = (const float*)d_in[idx];
        else if (in_sizes[idx] == NOUT * DDIM)              bias = (const float*)d_in[idx];
    }
    k1_uhat<<<NIN, 320>>>(x, W);
    k2_route<<<BATCH, K2_THREADS>>>(bias, (float*)d_out);
}

// round 6
// speedup vs baseline: 1.6641x; 1.0300x over previous
#include <cuda_runtime.h>
#include <cuda_fp16.h>

// Problem constants
#define BATCH 128
#define NIN   1152
#define DIN   8
#define NOUT  10
#define DDIM  16
#define FDIM  160
#define ROWSZ ((size_t)NIN * FDIM)
#define SQ_EPS 1e-7f

#define K2_THREADS 768
#define K2_WARPS   24
#define I_PER_WARP 48
#define K2_ITERS   16

typedef unsigned long long ull;

// u_hat scratch: [BATCH][NIN][FDIM] fp16 = 47.2 MB (L2-resident)
__device__ __half g_uhat[(size_t)BATCH * ROWSZ];

// ---------------- packed f32x2 helpers -------------------------------------
__device__ __forceinline__ ull pk2(float lo, float hi) {
    ull r; asm("mov.b64 %0, {%1, %2};" : "=l"(r) : "f"(lo), "f"(hi)); return r;
}
__device__ __forceinline__ void upk2(ull v, float& lo, float& hi) {
    asm("mov.b64 {%0, %1}, %2;" : "=f"(lo), "=f"(hi) : "l"(v));
}
__device__ __forceinline__ ull fma2(ull a, ull b, ull c) {
    ull d; asm("fma.rn.f32x2 %0, %1, %2, %3;" : "=l"(d) : "l"(a), "l"(b), "l"(c)); return d;
}
__device__ __forceinline__ ull mul2(ull a, ull b) {
    ull d; asm("mul.rn.f32x2 %0, %1, %2;" : "=l"(d) : "l"(a), "l"(b)); return d;
}
__device__ __forceinline__ ull add2(ull a, ull b) {
    ull d; asm("add.rn.f32x2 %0, %1, %2;" : "=l"(d) : "l"(a), "l"(b)); return d;
}
__device__ __forceinline__ ull h2_to_f2(unsigned h2) {
    ull r;
    asm("{\n\t"
        ".reg .b16 l, h;\n\t"
        ".reg .f32 fl, fh;\n\t"
        "mov.b32 {l, h}, %1;\n\t"
        "cvt.f32.f16 fl, l;\n\t"
        "cvt.f32.f16 fh, h;\n\t"
        "mov.b64 %0, {fl, fh};\n\t"
        "}" : "=l"(r) : "r"(h2));
    return r;
}

// ---------------------------------------------------------------------------
// K1: u_hat[b,i,f] = sum_k W[i,f,k] * x[b,i,k]  -> fp16 store.
// EXACT R2 structure (measured 10.3 us): one block per i, thread owns an
// f-pair, scalar FMA, coalesced half2 stores.
// ---------------------------------------------------------------------------
__global__ __launch_bounds__(320) void k1_uhat(const float* __restrict__ x,
                                               const float* __restrict__ W) {
    const int i = blockIdx.x;                 // 0..1151
    __shared__ __align__(16) float Ws[FDIM * DIN];   // 5 KB
    __shared__ __align__(16) float xs[BATCH * DIN];  // 4 KB
    const int tid = threadIdx.x;

    for (int t = tid; t < FDIM * DIN; t += 320)
        Ws[t] = W[(size_t)i * (FDIM * DIN) + t];
    for (int t = tid; t < BATCH * DIN; t += 320) {
        const int b = t / DIN, k = t % DIN;
        xs[t] = x[((size_t)b * NIN + i) * DIN + k];
    }
    __syncthreads();

    const int f2 = tid % 80;   // pair index: covers f = 2*f2, 2*f2+1
    const int b0 = tid / 80;   // 0..3

    float wA[DIN], wB[DIN];
#pragma unroll
    for (int k = 0; k < DIN; k++) {
        wA[k] = Ws[(2 * f2) * DIN + k];
        wB[k] = Ws[(2 * f2 + 1) * DIN + k];
    }

    __half2* __restrict__ uh2 = reinterpret_cast<__half2*>(g_uhat);

    for (int b = b0; b < BATCH; b += 4) {
        const float4 xa = *reinterpret_cast<const float4*>(&xs[b * DIN]);
        const float4 xb = *reinterpret_cast<const float4*>(&xs[b * DIN + 4]);
        float a0 = wA[0] * xa.x, a1 = wB[0] * xa.x;
        a0 = fmaf(wA[1], xa.y, a0);  a1 = fmaf(wB[1], xa.y, a1);
        a0 = fmaf(wA[2], xa.z, a0);  a1 = fmaf(wB[2], xa.z, a1);
        a0 = fmaf(wA[3], xa.w, a0);  a1 = fmaf(wB[3], xa.w, a1);
        a0 = fmaf(wA[4], xb.x, a0);  a1 = fmaf(wB[4], xb.x, a1);
        a0 = fmaf(wA[5], xb.y, a0);  a1 = fmaf(wB[5], xb.y, a1);
        a0 = fmaf(wA[6], xb.z, a0);  a1 = fmaf(wB[6], xb.z, a1);
        a0 = fmaf(wA[7], xb.w, a0);  a1 = fmaf(wB[7], xb.w, a1);
        uh2[((size_t)b * NIN + i) * (FDIM / 2) + f2] = __floats2half2_rn(a0, a1);
    }
}

// ---------------------------------------------------------------------------
// K2: fused 3-iteration dynamic routing, one block (768 thr) per b.
// R5 structure + tree-summed esum (shorter dependent chain).
// ---------------------------------------------------------------------------
__global__ __launch_bounds__(K2_THREADS) void k2_route(const float* __restrict__ bias,
                                                       float* __restrict__ out) {
    const int b   = blockIdx.x;
    const int tid = threadIdx.x;
    const int w   = tid >> 5;
    const int l   = tid & 31;
    const bool active = (l < 30);
    const int g = active ? (l / 10) : 0;
    const int j = active ? (l % 10) : 0;

    __shared__ float s_part[K2_WARPS][FDIM];
    __shared__ float s_red[FDIM];
    __shared__ float vsum_sm[FDIM];
    __shared__ float vlast_sm[FDIM];
    __shared__ float bias_sm[FDIM];

    if (tid < FDIM) bias_sm[tid] = bias[tid];

    const __half* __restrict__ ubase = g_uhat + (size_t)b * ROWSZ;
    const unsigned FULL = 0xFFFFFFFFu;

    for (int pass = 0; pass < 3; ++pass) {
        ull vr2[8];
        if (pass > 0) {
#pragma unroll
            for (int m = 0; m < 8; m++)
                vr2[m] = pk2(vsum_sm[j * DDIM + 2 * m], vsum_sm[j * DDIM + 2 * m + 1]);
        }
        ull sacc2[8];
#pragma unroll
        for (int m = 0; m < 8; m++) sacc2[m] = 0ull;

        uint4 p0 = make_uint4(0, 0, 0, 0), p1 = make_uint4(0, 0, 0, 0);
        {
            const int i = w * I_PER_WARP + g;
            if (active) {
                const uint4* up = reinterpret_cast<const uint4*>(
                    ubase + (size_t)i * FDIM + j * DDIM);
                p0 = up[0]; p1 = up[1];
            }
        }

        for (int it = 0; it < K2_ITERS; ++it) {
            uint4 n0 = make_uint4(0, 0, 0, 0), n1 = make_uint4(0, 0, 0, 0);
            if (it + 1 < K2_ITERS && active) {
                const int ni = w * I_PER_WARP + (it + 1) * 3 + g;
                const uint4* up = reinterpret_cast<const uint4*>(
                    ubase + (size_t)ni * FDIM + j * DDIM);
                n0 = up[0]; n1 = up[1];
            }

            ull u2[8];
            u2[0] = h2_to_f2(p0.x); u2[1] = h2_to_f2(p0.y);
            u2[2] = h2_to_f2(p0.z); u2[3] = h2_to_f2(p0.w);
            u2[4] = h2_to_f2(p1.x); u2[5] = h2_to_f2(p1.y);
            u2[6] = h2_to_f2(p1.z); u2[7] = h2_to_f2(p1.w);

            if (pass == 0) {
#pragma unroll
                for (int m = 0; m < 8; m++) sacc2[m] = add2(sacc2[m], u2[m]);
            } else {
                ull a2 = mul2(u2[0], vr2[0]);
#pragma unroll
                for (int m = 1; m < 8; m++) a2 = fma2(u2[m], vr2[m], a2);
                float alo, ahi; upk2(a2, alo, ahi);
                float a = alo + ahi;
                a = fmaxf(fminf(a, 60.f), -60.f);
                const float e = __expf(a);
                // gather 10 exp's (independent shfls), tree-add (short dep chain)
                float ev[NOUT];
#pragma unroll
                for (int jj = 0; jj < NOUT; jj++)
                    ev[jj] = __shfl_sync(FULL, e, g * 10 + jj);
                const float s01 = ev[0] + ev[1];
                const float s23 = ev[2] + ev[3];
                const float s45 = ev[4] + ev[5];
                const float s67 = ev[6] + ev[7];
                const float s89 = ev[8] + ev[9];
                const float esum = ((s01 + s23) + (s45 + s67)) + s89;
                const float c = __fdividef(e, esum);
                const ull c2 = pk2(c, c);
#pragma unroll
                for (int m = 0; m < 8; m++) sacc2[m] = fma2(c2, u2[m], sacc2[m]);
            }
            p0 = n0; p1 = n1;
        }

#pragma unroll
        for (int m = 0; m < 8; m++) {
            const ull t1 = __shfl_down_sync(FULL, sacc2[m], 10);
            const ull t2 = __shfl_down_sync(FULL, sacc2[m], 20);
            sacc2[m] = add2(sacc2[m], add2(t1, t2));
        }
        if (l < NOUT) {
#pragma unroll
            for (int m = 0; m < 8; m++)
                *reinterpret_cast<ull*>(&s_part[w][l * DDIM + 2 * m]) = sacc2[m];
        }
        __syncthreads();

        if (tid < FDIM) {
            float acc = 0.f;
#pragma unroll
            for (int ww = 0; ww < K2_WARPS; ww++) acc += s_part[ww][tid];
            if (pass == 0) acc *= (1.0f / NOUT);
            s_red[tid] = acc + bias_sm[tid];
        }
        __syncthreads();

        if (tid < NOUT) {
            float sv[DDIM];
            float sq = 0.f;
#pragma unroll
            for (int d = 0; d < DDIM; d++) {
                sv[d] = s_red[tid * DDIM + d];
                sq = fmaf(sv[d], sv[d], sq);
            }
            const float scale = sq / (1.0f + sq) * rsqrtf(sq + SQ_EPS);
#pragma unroll
            for (int d = 0; d < DDIM; d++) {
                const float v = scale * sv[d];
                vlast_sm[tid * DDIM + d] = v;
                if (pass == 0)      vsum_sm[tid * DDIM + d] = v;
                else if (pass == 1) vsum_sm[tid * DDIM + d] += v;
            }
        }
        __syncthreads();
    }

    if (tid < FDIM) out[(size_t)b * FDIM + tid] = vlast_sm[tid];
}

// ---------------------------------------------------------------------------
extern "C" void kernel_launch(void* const* d_in, const int* in_sizes, int n_in,
                              void* d_out, int out_size) {
    const float* x = nullptr;
    const float* W = nullptr;
    const float* bias = nullptr;
    for (int idx = 0; idx < n_in; ++idx) {
        if (in_sizes[idx] == BATCH * NIN * DIN)             x    = (const float*)d_in[idx];
        else if (in_sizes[idx] == NIN * NOUT * DDIM * DIN)  W    = (const float*)d_in[idx];
        else if (in_sizes[idx] == NOUT * DDIM)              bias = (const float*)d_in[idx];
    }
    k1_uhat<<<NIN, 320>>>(x, W);
    k2_route<<<BATCH, K2_THREADS>>>(bias, (float*)d_out);
}

// round 7
// speedup vs baseline: 1.7704x; 1.0639x over previous
#include <cuda_runtime.h>
#include <cuda_fp16.h>

// Problem constants
#define BATCH 128
#define NIN   1152
#define DIN   8
#define NOUT  10
#define DDIM  16
#define FDIM  160
#define NTRI  (NIN / 3)          // 384 i-triples
#define TRIH  512                // halves per triple block (960 used + 64 pad)
#define ROWH  ((size_t)NTRI * TRIH)  // halves per batch row = 196608
#define SQ_EPS 1e-7f

#define K2_THREADS 768
#define K2_WARPS   24
#define K2_ITERS   16            // triples per warp (16*24 = 384)

typedef unsigned long long ull;

// u_hat scratch, i-triple-blocked layout:
//   half index = ((b*NTRI + t)*TRIH) + q*256 + lane*8 + h
//   where t=i/3, lane=(i%3)*10+j (0..29; 30,31 pad), q=d/8, h=d%8
// 128 * 384 * 512 halves = 50.3 MB (L2-resident)
__device__ __half g_uhat[(size_t)BATCH * ROWH];

// ---------------- packed f32x2 helpers -------------------------------------
__device__ __forceinline__ ull pk2(float lo, float hi) {
    ull r; asm("mov.b64 %0, {%1, %2};" : "=l"(r) : "f"(lo), "f"(hi)); return r;
}
__device__ __forceinline__ void upk2(ull v, float& lo, float& hi) {
    asm("mov.b64 {%0, %1}, %2;" : "=f"(lo), "=f"(hi) : "l"(v));
}
__device__ __forceinline__ ull fma2(ull a, ull b, ull c) {
    ull d; asm("fma.rn.f32x2 %0, %1, %2, %3;" : "=l"(d) : "l"(a), "l"(b), "l"(c)); return d;
}
__device__ __forceinline__ ull mul2(ull a, ull b) {
    ull d; asm("mul.rn.f32x2 %0, %1, %2;" : "=l"(d) : "l"(a), "l"(b)); return d;
}
__device__ __forceinline__ ull add2(ull a, ull b) {
    ull d; asm("add.rn.f32x2 %0, %1, %2;" : "=l"(d) : "l"(a), "l"(b)); return d;
}
__device__ __forceinline__ ull h2_to_f2(unsigned h2) {
    ull r;
    asm("{\n\t"
        ".reg .b16 l, h;\n\t"
        ".reg .f32 fl, fh;\n\t"
        "mov.b32 {l, h}, %1;\n\t"
        "cvt.f32.f16 fl, l;\n\t"
        "cvt.f32.f16 fh, h;\n\t"
        "mov.b64 %0, {fl, fh};\n\t"
        "}" : "=l"(r) : "r"(h2));
    return r;
}

// ---------------------------------------------------------------------------
// K1: u_hat[b,i,f] = sum_k W[i,f,k] * x[b,i,k]  -> fp16, triple-blocked store.
// One block per i; thread owns an f-pair (same j, consecutive d's, same q).
// ---------------------------------------------------------------------------
__global__ __launch_bounds__(320) void k1_uhat(const float* __restrict__ x,
                                               const float* __restrict__ W) {
    const int i = blockIdx.x;                 // 0..1151
    const int t = i / 3;
    const int g = i % 3;
    __shared__ __align__(16) float Ws[FDIM * DIN];   // 5 KB
    __shared__ __align__(16) float xs[BATCH * DIN];  // 4 KB
    const int tid = threadIdx.x;

    for (int tt = tid; tt < FDIM * DIN; tt += 320)
        Ws[tt] = W[(size_t)i * (FDIM * DIN) + tt];
    for (int tt = tid; tt < BATCH * DIN; tt += 320) {
        const int b = tt / DIN, k = tt % DIN;
        xs[tt] = x[((size_t)b * NIN + i) * DIN + k];
    }
    __syncthreads();

    const int f2 = tid % 80;   // pair: fA=2*f2, fB=2*f2+1 (same j, same q)
    const int b0 = tid / 80;   // 0..3
    const int j  = f2 / 8;            // 0..9
    const int dA = (f2 % 8) * 2;      // 0,2,...,14
    const int q  = dA >> 3;           // 0/1
    const int hh = dA & 7;            // even

    float wA[DIN], wB[DIN];
#pragma unroll
    for (int k = 0; k < DIN; k++) {
        wA[k] = Ws[(2 * f2) * DIN + k];
        wB[k] = Ws[(2 * f2 + 1) * DIN + k];
    }

    // half2 slot for (b, t, q, lane=g*10+j, hh)
    const size_t slot_h2 = ((size_t)t * TRIH + q * 256 + (g * 10 + j) * 8 + hh) / 2;
    __half2* __restrict__ uh2 = reinterpret_cast<__half2*>(g_uhat) + slot_h2;

    for (int b = b0; b < BATCH; b += 4) {
        const float4 xa = *reinterpret_cast<const float4*>(&xs[b * DIN]);
        const float4 xb = *reinterpret_cast<const float4*>(&xs[b * DIN + 4]);
        float a0 = wA[0] * xa.x, a1 = wB[0] * xa.x;
        a0 = fmaf(wA[1], xa.y, a0);  a1 = fmaf(wB[1], xa.y, a1);
        a0 = fmaf(wA[2], xa.z, a0);  a1 = fmaf(wB[2], xa.z, a1);
        a0 = fmaf(wA[3], xa.w, a0);  a1 = fmaf(wB[3], xa.w, a1);
        a0 = fmaf(wA[4], xb.x, a0);  a1 = fmaf(wB[4], xb.x, a1);
        a0 = fmaf(wA[5], xb.y, a0);  a1 = fmaf(wB[5], xb.y, a1);
        a0 = fmaf(wA[6], xb.z, a0);  a1 = fmaf(wB[6], xb.z, a1);
        a0 = fmaf(wA[7], xb.w, a0);  a1 = fmaf(wB[7], xb.w, a1);
        uh2[(size_t)b * (ROWH / 2)] = __floats2half2_rn(a0, a1);
    }
}

// ---------------------------------------------------------------------------
// K2: fused 3-iteration dynamic routing, one block (768 thr) per b.
// Triple-blocked loads: 2x LDG.128, each 32 lanes x 16B fully contiguous.
// ---------------------------------------------------------------------------
__global__ __launch_bounds__(K2_THREADS) void k2_route(const float* __restrict__ bias,
                                                       float* __restrict__ out) {
    const int b   = blockIdx.x;
    const int tid = threadIdx.x;
    const int w   = tid >> 5;
    const int l   = tid & 31;
    const bool active = (l < 30);
    const int g = active ? (l / 10) : 0;
    const int j = active ? (l % 10) : 0;

    __shared__ float s_part[K2_WARPS][FDIM];
    __shared__ float s_red[FDIM];
    __shared__ float vsum_sm[FDIM];
    __shared__ float vlast_sm[FDIM];
    __shared__ float bias_sm[FDIM];

    if (tid < FDIM) bias_sm[tid] = bias[tid];

    // per-lane base: all 32 lanes load (pad lanes harmless, results discarded)
    const uint4* __restrict__ ubase4 =
        reinterpret_cast<const uint4*>(g_uhat + (size_t)b * ROWH);
    const unsigned FULL = 0xFFFFFFFFu;

    for (int pass = 0; pass < 3; ++pass) {
        ull vr2[8];
        if (pass > 0) {
#pragma unroll
            for (int m = 0; m < 8; m++)
                vr2[m] = pk2(vsum_sm[j * DDIM + 2 * m], vsum_sm[j * DDIM + 2 * m + 1]);
        }
        ull sacc2[8];
#pragma unroll
        for (int m = 0; m < 8; m++) sacc2[m] = 0ull;

        // triple block for (w, it): 64 uint4 = 1024B; q0 at [l], q1 at [32+l]
        uint4 p0, p1;
        {
            const uint4* up = ubase4 + (size_t)(w * K2_ITERS) * 64 + l;
            p0 = up[0];
            p1 = up[32];
        }

        for (int it = 0; it < K2_ITERS; ++it) {
            uint4 n0, n1;
            if (it + 1 < K2_ITERS) {
                const uint4* up = ubase4 + (size_t)(w * K2_ITERS + it + 1) * 64 + l;
                n0 = up[0];
                n1 = up[32];
            } else {
                n0 = p0; n1 = p1;
            }

            ull u2[8];
            u2[0] = h2_to_f2(p0.x); u2[1] = h2_to_f2(p0.y);
            u2[2] = h2_to_f2(p0.z); u2[3] = h2_to_f2(p0.w);
            u2[4] = h2_to_f2(p1.x); u2[5] = h2_to_f2(p1.y);
            u2[6] = h2_to_f2(p1.z); u2[7] = h2_to_f2(p1.w);

            if (pass == 0) {
#pragma unroll
                for (int m = 0; m < 8; m++) sacc2[m] = add2(sacc2[m], u2[m]);
            } else {
                ull a2 = mul2(u2[0], vr2[0]);
#pragma unroll
                for (int m = 1; m < 8; m++) a2 = fma2(u2[m], vr2[m], a2);
                float alo, ahi; upk2(a2, alo, ahi);
                float a = alo + ahi;
                a = fmaxf(fminf(a, 60.f), -60.f);   // NaN/garbage-safe clamp
                const float e = __expf(a);
                float ev[NOUT];
#pragma unroll
                for (int jj = 0; jj < NOUT; jj++)
                    ev[jj] = __shfl_sync(FULL, e, g * 10 + jj);
                const float s01 = ev[0] + ev[1];
                const float s23 = ev[2] + ev[3];
                const float s45 = ev[4] + ev[5];
                const float s67 = ev[6] + ev[7];
                const float s89 = ev[8] + ev[9];
                const float esum = ((s01 + s23) + (s45 + s67)) + s89;
                const float c = __fdividef(e, esum);
                const ull c2 = pk2(c, c);
#pragma unroll
                for (int m = 0; m < 8; m++) sacc2[m] = fma2(c2, u2[m], sacc2[m]);
            }
            p0 = n0; p1 = n1;
        }

        // combine 3 groups (lanes l, l+10, l+20) -> lanes 0..9
#pragma unroll
        for (int m = 0; m < 8; m++) {
            const ull t1 = __shfl_down_sync(FULL, sacc2[m], 10);
            const ull t2 = __shfl_down_sync(FULL, sacc2[m], 20);
            sacc2[m] = add2(sacc2[m], add2(t1, t2));
        }
        if (l < NOUT) {
#pragma unroll
            for (int m = 0; m < 8; m++)
                *reinterpret_cast<ull*>(&s_part[w][l * DDIM + 2 * m]) = sacc2[m];
        }
        __syncthreads();

        if (tid < FDIM) {
            float acc = 0.f;
#pragma unroll
            for (int ww = 0; ww < K2_WARPS; ww++) acc += s_part[ww][tid];
            if (pass == 0) acc *= (1.0f / NOUT);
            s_red[tid] = acc + bias_sm[tid];
        }
        __syncthreads();

        if (tid < NOUT) {
            float sv[DDIM];
            float sq = 0.f;
#pragma unroll
            for (int d = 0; d < DDIM; d++) {
                sv[d] = s_red[tid * DDIM + d];
                sq = fmaf(sv[d], sv[d], sq);
            }
            const float scale = sq / (1.0f + sq) * rsqrtf(sq + SQ_EPS);
#pragma unroll
            for (int d = 0; d < DDIM; d++) {
                const float v = scale * sv[d];
                vlast_sm[tid * DDIM + d] = v;
                if (pass == 0)      vsum_sm[tid * DDIM + d] = v;
                else if (pass == 1) vsum_sm[tid * DDIM + d] += v;
            }
        }
        __syncthreads();
    }

    if (tid < FDIM) out[(size_t)b * FDIM + tid] = vlast_sm[tid];
}

// ---------------------------------------------------------------------------
extern "C" void kernel_launch(void* const* d_in, const int* in_sizes, int n_in,
                              void* d_out, int out_size) {
    const float* x = nullptr;
    const float* W = nullptr;
    const float* bias = nullptr;
    for (int idx = 0; idx < n_in; ++idx) {
        if (in_sizes[idx] == BATCH * NIN * DIN)             x    = (const float*)d_in[idx];
        else if (in_sizes[idx] == NIN * NOUT * DDIM * DIN)  W    = (const float*)d_in[idx];
        else if (in_sizes[idx] == NOUT * DDIM)              bias = (const float*)d_in[idx];
    }
    k1_uhat<<<NIN, 320>>>(x, W);
    k2_route<<<BATCH, K2_THREADS>>>(bias, (float*)d_out);
}